// round 12
// baseline (speedup 1.0000x reference)
#include <cuda_runtime.h>

#define NN 100000      // nodes
#define EE 1000000     // edges
#define HD 64          // hidden
#define GG 512         // graphs
#define EPS_GEN 1e-7f
#define EPS_BN  1e-5f

// ---------------- scratch (device globals; no allocations) ----------------
__device__ float g_h [NN * HD];
__device__ float g_h2[NN * HD];
__device__ float g_m [NN * HD];   // conv input: pre-seeded h_in, RED-accumulated msgs
__device__ float g_vt[GG * HD];
__device__ float g_vn[GG * HD];
__device__ float g_sum[HD];
__device__ float g_sq [HD];
__device__ float g_ga[HD];        // node-BN scale  (gamma * rstd)
__device__ float g_sh[HD];        // node-BN shift  (beta - mu*ga)
__device__ float g_vnsA[2 * HD];
__device__ float g_vnsB[2 * HD];
__device__ float g_cnt[GG];
// CSR by destination
__device__ int g_deg[NN];
__device__ int g_rowptr[NN];
__device__ int g_cur[NN];
__device__ int g_bsum[128];
__device__ int g_boff[128];
__device__ unsigned g_epk[EE];    // packed: src | a0<<17 | a1<<20 | a2<<23
__device__ int g_edst[EE];        // dst per sorted edge position

// ---------------- init: deg=0, cnt=0, vt=0, vn=vn0, stats=0 ---------------
__global__ void k_init(const float* __restrict__ vn0) {
    int i = blockIdx.x * blockDim.x + threadIdx.x;
    int stride = gridDim.x * blockDim.x;
    for (int j = i; j < NN; j += stride) g_deg[j] = 0;
    if (i < GG) g_cnt[i] = 0.f;
    if (i < GG * HD) { g_vn[i] = vn0[i & 63]; g_vt[i] = 0.f; }
    if (i < HD) { g_sum[i] = 0.f; g_sq[i] = 0.f; }
}

// ---------------- node counts per graph (run-length, batch sorted) --------
__global__ void k_cnt(const int* __restrict__ batch) {
    int t = blockIdx.x * blockDim.x + threadIdx.x;
    int base = t * 32;
    if (base >= NN) return;
    int end = min(base + 32, NN);
    int cur = batch[base];
    float acc = 0.f;
    for (int r = base; r < end; r++) {
        int b = batch[r];
        if (b != cur) { atomicAdd(&g_cnt[cur], acc); cur = b; acc = 0.f; }
        acc += 1.f;
    }
    atomicAdd(&g_cnt[cur], acc);
}

// ---------------- atom encoder: h = sum_f atom_table[x+off] + vn0 ---------
// also seeds g_m = h for the layer-0 edge-parallel gather
__global__ void k_atom(const float4* __restrict__ atab,
                       const int* __restrict__ x,
                       const float4* __restrict__ vn0) {
    int t = blockIdx.x * blockDim.x + threadIdx.x;
    int n = t >> 4, lane = t & 15;
    if (n >= NN) return;
    const int aoff[9] = {0, 119, 124, 136, 148, 158, 164, 170, 172};
    float4 a = __ldg(&vn0[lane]);
#pragma unroll
    for (int i = 0; i < 9; i++) {
        int idx = __ldg(&x[n * 9 + i]) + aoff[i];
        float4 v = __ldg(&atab[idx * 16 + lane]);
        a.x += v.x; a.y += v.y; a.z += v.z; a.w += v.w;
    }
    ((float4*)g_h)[n * 16 + lane] = a;
    ((float4*)g_m)[n * 16 + lane] = a;
}

// ================= CSR build (per call; edges static within call) =========
__global__ void k_hist(const int* __restrict__ ei) {
    int e = blockIdx.x * 256 + threadIdx.x;
    if (e >= EE) return;
    atomicAdd(&g_deg[__ldg(&ei[EE + e])], 1);
}

__global__ void k_scan1() {   // 98 blocks x 1024: chunk sums
    __shared__ int ws[32];
    int b = blockIdx.x, tid = threadIdx.x;
    int i = b * 1024 + tid;
    int v = (i < NN) ? g_deg[i] : 0;
    int s = v;
#pragma unroll
    for (int o = 16; o; o >>= 1) s += __shfl_down_sync(~0u, s, o);
    if ((tid & 31) == 0) ws[tid >> 5] = s;
    __syncthreads();
    if (tid < 32) {
        int t = ws[tid];
#pragma unroll
        for (int o = 16; o; o >>= 1) t += __shfl_down_sync(~0u, t, o);
        if (tid == 0) g_bsum[b] = t;
    }
}

__global__ void k_scan2() {   // 1 block x 128: exclusive scan of chunk sums
    __shared__ int sm[128];
    int tid = threadIdx.x;
    int nb = (NN + 1023) / 1024;
    int v = (tid < nb) ? g_bsum[tid] : 0;
    sm[tid] = v; __syncthreads();
    for (int o = 1; o < 128; o <<= 1) {
        int t = (tid >= o) ? sm[tid - o] : 0;
        __syncthreads();
        sm[tid] += t;
        __syncthreads();
    }
    g_boff[tid] = sm[tid] - v;
}

__global__ void k_scan3() {   // 98 blocks x 1024: rowptr + cursor
    __shared__ int sm[1024];
    int b = blockIdx.x, tid = threadIdx.x;
    int i = b * 1024 + tid;
    int v = (i < NN) ? g_deg[i] : 0;
    sm[tid] = v; __syncthreads();
    for (int o = 1; o < 1024; o <<= 1) {
        int t = (tid >= o) ? sm[tid - o] : 0;
        __syncthreads();
        sm[tid] += t;
        __syncthreads();
    }
    if (i < NN) {
        int r = g_boff[b] + sm[tid] - v;   // exclusive
        g_rowptr[i] = r;
        g_cur[i] = r;
    }
}

__global__ void k_fill(const int* __restrict__ ei, const int* __restrict__ ea) {
    int e = blockIdx.x * 256 + threadIdx.x;
    if (e >= EE) return;
    int dst = __ldg(&ei[EE + e]);
    int p = atomicAdd(&g_cur[dst], 1);
    unsigned pk = (unsigned)__ldg(&ei[e])
                | ((unsigned)__ldg(&ea[e * 3 + 0]) << 17)
                | ((unsigned)__ldg(&ea[e * 3 + 1]) << 20)
                | ((unsigned)__ldg(&ea[e * 3 + 2]) << 23);
    g_epk[p] = pk;
    g_edst[p] = dst;
}

// ====== edge-parallel gather with segmented RED ===========================
// half-warp (16 lanes, float4) per 16-edge chunk of the dst-sorted list.
// All 16 h[src] loads issued up-front (MLP=16); run-length reduce; one
// red.global.add.v4 per segment. g_m is pre-seeded with h_in.
#define NCHUNK (EE / 16)          // 62500
__device__ __forceinline__ void red4(float* p, float4 v) {
    asm volatile("red.global.add.v4.f32 [%0], {%1,%2,%3,%4};"
                 :: "l"(p), "f"(v.x), "f"(v.y), "f"(v.z), "f"(v.w)
                 : "memory");
}

__global__ void __launch_bounds__(256) k_gather_ep(int use_h2,
                                                   const float4* __restrict__ btab4) {
    __shared__ float4 comb[960];   // 60 combos x 16 float4 = 15KB
    int tid = threadIdx.x;
    for (int i = tid; i < 960; i += 256) {
        int c = i >> 4, f = i & 15;
        int a0 = c % 5, t = c / 5, a1 = t % 6, a2 = t / 6;
        float4 v0 = __ldg(&btab4[a0 * 16 + f]);
        float4 v1 = __ldg(&btab4[(5 + a1) * 16 + f]);
        float4 v2 = __ldg(&btab4[(11 + a2) * 16 + f]);
        comb[i] = make_float4(v0.x + v1.x + v2.x, v0.y + v1.y + v2.y,
                              v0.z + v1.z + v2.z, v0.w + v1.w + v2.w);
    }
    __syncthreads();

    const float4* __restrict__ hin =
        use_h2 ? (const float4*)g_h2 : (const float4*)g_h;

    int lane = tid & 15;
    int chunk = blockIdx.x * 16 + (tid >> 4);
    // NCHUNK % 16 == 4: in the tail block, invalid half-warps pair up into
    // whole warps (subs {4,5},{6,7},...), so full-mask shfl below stays legal.
    if (chunk >= NCHUNK) return;
    int base = chunk * 16;

    unsigned pk = __ldg(&g_epk[base + lane]);
    int dstl    = __ldg(&g_edst[base + lane]);

    float4 hv[16];
#pragma unroll
    for (int e = 0; e < 16; e++) {
        unsigned p = __shfl_sync(0xffffffffu, pk, e, 16);
        hv[e] = __ldg(&hin[(p & 0x1FFFF) * 16 + lane]);
    }

    int cur = -1;
    float4 acc = make_float4(0.f, 0.f, 0.f, 0.f);
#pragma unroll
    for (int e = 0; e < 16; e++) {
        unsigned p = __shfl_sync(0xffffffffu, pk, e, 16);
        int d      = __shfl_sync(0xffffffffu, dstl, e, 16);
        int c = ((p >> 17) & 7) + 5 * ((p >> 20) & 7) + 30 * ((p >> 23) & 1);
        float4 em = comb[c * 16 + lane];
        float4 m;
        m.x = fmaxf(hv[e].x + em.x, 0.f) + EPS_GEN;
        m.y = fmaxf(hv[e].y + em.y, 0.f) + EPS_GEN;
        m.z = fmaxf(hv[e].z + em.z, 0.f) + EPS_GEN;
        m.w = fmaxf(hv[e].w + em.w, 0.f) + EPS_GEN;
        if (d != cur) {
            if (cur >= 0) red4(g_m + (size_t)cur * 64 + lane * 4, acc);
            cur = d;
            acc = m;
        } else {
            acc.x += m.x; acc.y += m.y; acc.z += m.z; acc.w += m.w;
        }
    }
    red4(g_m + (size_t)cur * 64 + lane * 4, acc);
}

// ---------------- g_m @ W + b (+res) -> g_h ; fused BN stats --------------
__global__ void __launch_bounds__(256) k_matmul(int layer0,
                                                const float* __restrict__ W,
                                                const float* __restrict__ bias) {
    __shared__ __align__(16) float W_sh[64 * 64];
    __shared__ float in_sh[64][65];
    __shared__ float s_sum[64], s_sq[64];
    int tid = threadIdx.x;
    int base = blockIdx.x * 64;
    {
        const float4* W4 = (const float4*)W;
        float4* Ws4 = (float4*)W_sh;
#pragma unroll
        for (int i = 0; i < 4; i++) Ws4[tid + i * 256] = __ldg(&W4[tid + i * 256]);
    }
#pragma unroll
    for (int i = 0; i < 16; i++) {
        int idx = tid + i * 256;
        int r = idx >> 6, f = idx & 63;
        int row = base + r;
        in_sh[r][f] = (row < NN) ? g_m[row * 64 + f] : 0.f;
    }
    if (tid < 64) { s_sum[tid] = 0.f; s_sq[tid] = 0.f; }
    __syncthreads();

    int ng = tid >> 4, cg = tid & 15;
    float acc[4][4];
#pragma unroll
    for (int i = 0; i < 4; i++)
#pragma unroll
        for (int j = 0; j < 4; j++) acc[i][j] = 0.f;
#pragma unroll 8
    for (int k = 0; k < 64; k++) {
        float4 w = *(const float4*)&W_sh[k * 64 + cg * 4];
#pragma unroll
        for (int i = 0; i < 4; i++) {
            float iv = in_sh[ng * 4 + i][k];
            acc[i][0] = fmaf(iv, w.x, acc[i][0]);
            acc[i][1] = fmaf(iv, w.y, acc[i][1]);
            acc[i][2] = fmaf(iv, w.z, acc[i][2]);
            acc[i][3] = fmaf(iv, w.w, acc[i][3]);
        }
    }
    float4 bv = __ldg((const float4*)bias + cg);
    float csum[4] = {0, 0, 0, 0}, csq[4] = {0, 0, 0, 0};
#pragma unroll
    for (int i = 0; i < 4; i++) {
        int row = base + ng * 4 + i;
        if (row < NN) {
            float4 o;
            o.x = acc[i][0] + bv.x; o.y = acc[i][1] + bv.y;
            o.z = acc[i][2] + bv.z; o.w = acc[i][3] + bv.w;
            if (!layer0) {
                float4 r = *((const float4*)g_h + row * 16 + cg);
                o.x += r.x; o.y += r.y; o.z += r.z; o.w += r.w;
            }
            *((float4*)g_h + row * 16 + cg) = o;
            csum[0] += o.x; csq[0] += o.x * o.x;
            csum[1] += o.y; csq[1] += o.y * o.y;
            csum[2] += o.z; csq[2] += o.z * o.z;
            csum[3] += o.w; csq[3] += o.w * o.w;
        }
    }
#pragma unroll
    for (int j = 0; j < 4; j++) {
        atomicAdd(&s_sum[cg * 4 + j], csum[j]);
        atomicAdd(&s_sq [cg * 4 + j], csq[j]);
    }
    __syncthreads();
    if (tid < 64) {
        atomicAdd(&g_sum[tid], s_sum[tid]);
        atomicAdd(&g_sq [tid], s_sq[tid]);
    }
}

// ---- pool relu(BN(h)) -> vt (read-only); zero vn stats -------------------
__global__ void __launch_bounds__(256) k_bn_pool(const float* __restrict__ gamma,
                                                 const float* __restrict__ beta,
                                                 const int* __restrict__ batch) {
    int tid = threadIdx.x;
    int f = tid & 63;
    float mu = g_sum[f] * (1.f / NN);
    float var = g_sq[f] * (1.f / NN) - mu * mu;
    float ga = gamma[f] * rsqrtf(var + EPS_BN);
    float sh = beta[f] - mu * ga;
    if (blockIdx.x == 0 && tid < 128) { g_vnsA[tid] = 0.f; g_vnsB[tid] = 0.f; }
    int base = blockIdx.x * 256;
    int r0 = base + (tid >> 6);
    int rend = min(base + 256, NN);
    int cur = -1;
    float acc = 0.f;
    for (int r = r0; r < rend; r += 4) {
        float v = fmaxf(fmaf(g_h[r * 64 + f], ga, sh), 0.f);
        int b = __ldg(&batch[r]);
        if (b != cur) {
            if (cur >= 0) atomicAdd(&g_vt[cur * 64 + f], acc);
            cur = b; acc = v;
        } else acc += v;
    }
    if (cur >= 0) atomicAdd(&g_vt[cur * 64 + f], acc);
}

// ---- virtual node MLP ----------------------------------------------------
__global__ void k_vn_a(const float* __restrict__ W1, const float* __restrict__ b1) {
    __shared__ float row[64];
    int g = blockIdx.x, j = threadIdx.x;
    row[j] = g_vt[g * 64 + j] + g_vn[g * 64 + j];
    __syncthreads();
    float acc = __ldg(&b1[j]);
#pragma unroll
    for (int k = 0; k < 64; k++) acc = fmaf(row[k], __ldg(&W1[k * 64 + j]), acc);
    g_vt[g * 64 + j] = acc;
    atomicAdd(&g_vnsA[j], acc);
    atomicAdd(&g_vnsA[64 + j], acc * acc);
}

__global__ void k_vn_b(const float* __restrict__ g1, const float* __restrict__ be1,
                       const float* __restrict__ W2, const float* __restrict__ b2) {
    __shared__ float z[64];
    int g = blockIdx.x, j = threadIdx.x;
    float mu = g_vnsA[j] * (1.f / GG);
    float var = g_vnsA[64 + j] * (1.f / GG) - mu * mu;
    float ga = __ldg(&g1[j]) * rsqrtf(var + EPS_BN);
    float y = g_vt[g * 64 + j];
    z[j] = fmaxf((y - mu) * ga + __ldg(&be1[j]), 0.f);
    __syncthreads();
    float acc = __ldg(&b2[j]);
#pragma unroll
    for (int k = 0; k < 64; k++) acc = fmaf(z[k], __ldg(&W2[k * 64 + j]), acc);
    g_vt[g * 64 + j] = acc;
    atomicAdd(&g_vnsB[j], acc);
    atomicAdd(&g_vnsB[64 + j], acc * acc);
}

// ---- vn = relu(BN2(y2)); also precompute node-BN coeffs ga/sh ------------
__global__ void k_vn_c(const float* __restrict__ g2, const float* __restrict__ be2,
                       const float* __restrict__ gamma, const float* __restrict__ beta) {
    int i = blockIdx.x * blockDim.x + threadIdx.x;
    if (i < HD) {   // node-BN coefficients for k_h2
        float mu = g_sum[i] * (1.f / NN);
        float var = g_sq[i] * (1.f / NN) - mu * mu;
        float ga = gamma[i] * rsqrtf(var + EPS_BN);
        g_ga[i] = ga;
        g_sh[i] = beta[i] - mu * ga;
    }
    if (i >= GG * HD) return;
    int j = i & 63;
    float mu = g_vnsB[j] * (1.f / GG);
    float var = g_vnsB[64 + j] * (1.f / GG) - mu * mu;
    float ga = __ldg(&g2[j]) * rsqrtf(var + EPS_BN);
    g_vn[i] = fmaxf((g_vt[i] - mu) * ga + __ldg(&be2[j]), 0.f);
}

// ---- h2 = relu(BN(h)) + vn[batch]; seed g_m = h2; zero stats + vt --------
__global__ void __launch_bounds__(256) k_h2(const int* __restrict__ batch) {
    int idx = blockIdx.x * 256 + threadIdx.x;   // float4 index
    if (blockIdx.x == 0 && threadIdx.x < 64) {
        g_sum[threadIdx.x] = 0.f;
        g_sq[threadIdx.x] = 0.f;
    }
    if (blockIdx.x == 1) {
        for (int i = threadIdx.x; i < GG * HD; i += 256) g_vt[i] = 0.f;
    }
    if (idx >= NN * 16) return;
    int n = idx >> 4, fq = idx & 15;
    int b = __ldg(&batch[n]);
    float4 h = ((const float4*)g_h)[idx];
    float4 vn = __ldg((const float4*)g_vn + b * 16 + fq);
    float4 ga = *((const float4*)g_ga + fq);
    float4 sh = *((const float4*)g_sh + fq);
    float4 o;
    o.x = fmaxf(fmaf(h.x, ga.x, sh.x), 0.f) + vn.x;
    o.y = fmaxf(fmaf(h.y, ga.y, sh.y), 0.f) + vn.y;
    o.z = fmaxf(fmaf(h.z, ga.z, sh.z), 0.f) + vn.z;
    o.w = fmaxf(fmaf(h.w, ga.w, sh.w), 0.f) + vn.w;
    ((float4*)g_h2)[idx] = o;
    ((float4*)g_m)[idx] = o;     // seed for edge-parallel RED accumulation
}

// ---- pool: vt[g] = segment_sum(h) (raw h; final readout) -----------------
__global__ void __launch_bounds__(256) k_pool(const int* __restrict__ batch) {
    int tid = threadIdx.x;
    int f = tid & 63;
    int base = blockIdx.x * 256;
    int r0 = base + (tid >> 6);
    int rend = min(base + 256, NN);
    int cur = -1;
    float acc = 0.f;
    for (int r = r0; r < rend; r += 4) {
        float v = g_h[r * 64 + f];
        int b = __ldg(&batch[r]);
        if (b != cur) {
            if (cur >= 0) atomicAdd(&g_vt[cur * 64 + f], acc);
            cur = b; acc = v;
        } else acc += v;
    }
    if (cur >= 0) atomicAdd(&g_vt[cur * 64 + f], acc);
}

// ---- out = (vt/clip(cnt,1) - mu)*rstd*gamma + beta -----------------------
__global__ void k_final(float* __restrict__ out,
                        const float* __restrict__ gamma,
                        const float* __restrict__ beta) {
    int i = blockIdx.x * blockDim.x + threadIdx.x;
    if (i >= GG * HD) return;
    int g = i >> 6, f = i & 63;
    float mu = g_sum[f] * (1.f / NN);
    float var = g_sq[f] * (1.f / NN) - mu * mu;
    float rstd = rsqrtf(var + EPS_BN);
    float c = fmaxf(g_cnt[g], 1.f);
    out[i] = (g_vt[i] / c - mu) * rstd * __ldg(&gamma[f]) + __ldg(&beta[f]);
}

// =========================================================================
extern "C" void kernel_launch(void* const* d_in, const int* in_sizes, int n_in,
                              void* d_out, int out_size) {
    const float* atab  = (const float*)d_in[0];
    const float* btab  = (const float*)d_in[1];
    const float* vn0   = (const float*)d_in[2];
    const float* gcnW  = (const float*)d_in[3];
    const float* gcnb  = (const float*)d_in[4];
    const float* ngam  = (const float*)d_in[5];
    const float* nbet  = (const float*)d_in[6];
    const float* vnW1  = (const float*)d_in[7];
    const float* vnb1  = (const float*)d_in[8];
    const float* vng1  = (const float*)d_in[9];
    const float* vnbe1 = (const float*)d_in[10];
    const float* vnW2  = (const float*)d_in[11];
    const float* vnb2  = (const float*)d_in[12];
    const float* vng2  = (const float*)d_in[13];
    const float* vnbe2 = (const float*)d_in[14];
    const int*   x     = (const int*)d_in[15];
    const int*   ei    = (const int*)d_in[16];
    const int*   ea    = (const int*)d_in[17];
    const int*   batch = (const int*)d_in[18];
    float* out = (float*)d_out;

    const int MM_BLOCKS = (NN + 63) / 64;          // 1563
    const int SC_BLOCKS = (NN + 1023) / 1024;      // 98  (scans)
    const int PL_BLOCKS = (NN + 255) / 256;        // 391 (pool passes)
    const int E_BLOCKS  = (EE + 255) / 256;        // 3907
    const int H2_BLOCKS = (NN * 16 + 255) / 256;   // 6250
    const int EP_BLOCKS = (NCHUNK + 15) / 16;      // 3907

    // init + CSR build (integer atomics only)
    k_init<<<(NN + 255) / 256, 256>>>(vn0);
    k_cnt<<<(NN + 32 * 256 - 1) / (32 * 256), 256>>>(batch);
    k_atom<<<(NN * 16 + 255) / 256, 256>>>((const float4*)atab, x, (const float4*)vn0);
    k_hist<<<E_BLOCKS, 256>>>(ei);
    k_scan1<<<SC_BLOCKS, 1024>>>();
    k_scan2<<<1, 128>>>();
    k_scan3<<<SC_BLOCKS, 1024>>>();
    k_fill<<<E_BLOCKS, 256>>>(ei, ea);

    // layer 0: conv only (reads g_h; g_m seeded by k_atom)
    k_gather_ep<<<EP_BLOCKS, 256>>>(0, (const float4*)btab);
    k_matmul<<<MM_BLOCKS, 256>>>(1, gcnW, gcnb);

    // layers 1..6: BN->ReLU->vnode->conv->+res
    for (int l = 1; l < 7; l++) {
        int li = l - 1;
        k_bn_pool<<<PL_BLOCKS, 256>>>(ngam + li * 64, nbet + li * 64, batch);
        k_vn_a<<<GG, 64>>>(vnW1 + li * 4096, vnb1 + li * 64);
        k_vn_b<<<GG, 64>>>(vng1 + li * 64, vnbe1 + li * 64,
                           vnW2 + li * 4096, vnb2 + li * 64);
        k_vn_c<<<(GG * HD + 255) / 256, 256>>>(vng2 + li * 64, vnbe2 + li * 64,
                                               ngam + li * 64, nbet + li * 64);
        k_h2<<<H2_BLOCKS, 256>>>(batch);
        k_gather_ep<<<EP_BLOCKS, 256>>>(1, (const float4*)btab);
        k_matmul<<<MM_BLOCKS, 256>>>(0, gcnW + l * 4096, gcnb + l * 64);
    }

    // readout: mean pool of h, BN applied as affine on pooled mean
    k_pool<<<PL_BLOCKS, 256>>>(batch);
    k_final<<<(GG * HD + 255) / 256, 256>>>(out, ngam + 6 * 64, nbet + 6 * 64);
}

// round 13
// speedup vs baseline: 1.0200x; 1.0200x over previous
#include <cuda_runtime.h>

#define NN 100000      // nodes
#define EE 1000000     // edges
#define HD 64          // hidden
#define GG 512         // graphs
#define EPS_GEN 1e-7f
#define EPS_BN  1e-5f

// ---------------- scratch (device globals; no allocations) ----------------
__device__ float g_h [NN * HD];
__device__ float g_h2[NN * HD];
__device__ float g_m [NN * HD];   // conv input: h_in + aggregated messages
__device__ float g_vt[GG * HD];
__device__ float g_vn[GG * HD];
__device__ float g_sum[HD];
__device__ float g_sq [HD];
__device__ float g_ga[HD];        // node-BN scale  (gamma * rstd)
__device__ float g_sh[HD];        // node-BN shift  (beta - mu*ga)
__device__ float g_vnsA[2 * HD];
__device__ float g_vnsB[2 * HD];
__device__ float g_cnt[GG];
// CSR by destination
__device__ int g_deg[NN];
__device__ int g_rowptr[NN];
__device__ int g_cur[NN];
__device__ int g_bsum[128];
__device__ int g_boff[128];
__device__ unsigned g_epk[EE];    // packed: src | a0<<17 | a1<<20 | a2<<23

// ---------------- init: deg=0, cnt=0, vt=0, vn=vn0, stats=0 ---------------
__global__ void k_init(const float* __restrict__ vn0) {
    int i = blockIdx.x * blockDim.x + threadIdx.x;
    int stride = gridDim.x * blockDim.x;
    for (int j = i; j < NN; j += stride) g_deg[j] = 0;
    if (i < GG) g_cnt[i] = 0.f;
    if (i < GG * HD) { g_vn[i] = vn0[i & 63]; g_vt[i] = 0.f; }
    if (i < HD) { g_sum[i] = 0.f; g_sq[i] = 0.f; }
}

// ---------------- node counts per graph (run-length, batch sorted) --------
__global__ void k_cnt(const int* __restrict__ batch) {
    int t = blockIdx.x * blockDim.x + threadIdx.x;
    int base = t * 32;
    if (base >= NN) return;
    int end = min(base + 32, NN);
    int cur = batch[base];
    float acc = 0.f;
    for (int r = base; r < end; r++) {
        int b = batch[r];
        if (b != cur) { atomicAdd(&g_cnt[cur], acc); cur = b; acc = 0.f; }
        acc += 1.f;
    }
    atomicAdd(&g_cnt[cur], acc);
}

// ---------------- atom encoder: h = sum_f atom_table[x+off] + vn0 ---------
__global__ void k_atom(const float4* __restrict__ atab,
                       const int* __restrict__ x,
                       const float4* __restrict__ vn0) {
    int t = blockIdx.x * blockDim.x + threadIdx.x;
    int n = t >> 4, lane = t & 15;
    if (n >= NN) return;
    const int aoff[9] = {0, 119, 124, 136, 148, 158, 164, 170, 172};
    float4 a = __ldg(&vn0[lane]);
#pragma unroll
    for (int i = 0; i < 9; i++) {
        int idx = __ldg(&x[n * 9 + i]) + aoff[i];
        float4 v = __ldg(&atab[idx * 16 + lane]);
        a.x += v.x; a.y += v.y; a.z += v.z; a.w += v.w;
    }
    ((float4*)g_h)[n * 16 + lane] = a;
}

// ================= CSR build (per call; edges static within call) =========
__global__ void k_hist(const int* __restrict__ ei) {
    int e = blockIdx.x * 256 + threadIdx.x;
    if (e >= EE) return;
    atomicAdd(&g_deg[__ldg(&ei[EE + e])], 1);
}

__global__ void k_scan1() {   // 98 blocks x 1024: chunk sums
    __shared__ int ws[32];
    int b = blockIdx.x, tid = threadIdx.x;
    int i = b * 1024 + tid;
    int v = (i < NN) ? g_deg[i] : 0;
    int s = v;
#pragma unroll
    for (int o = 16; o; o >>= 1) s += __shfl_down_sync(~0u, s, o);
    if ((tid & 31) == 0) ws[tid >> 5] = s;
    __syncthreads();
    if (tid < 32) {
        int t = ws[tid];
#pragma unroll
        for (int o = 16; o; o >>= 1) t += __shfl_down_sync(~0u, t, o);
        if (tid == 0) g_bsum[b] = t;
    }
}

__global__ void k_scan2() {   // 1 block x 128: exclusive scan of chunk sums
    __shared__ int sm[128];
    int tid = threadIdx.x;
    int nb = (NN + 1023) / 1024;
    int v = (tid < nb) ? g_bsum[tid] : 0;
    sm[tid] = v; __syncthreads();
    for (int o = 1; o < 128; o <<= 1) {
        int t = (tid >= o) ? sm[tid - o] : 0;
        __syncthreads();
        sm[tid] += t;
        __syncthreads();
    }
    g_boff[tid] = sm[tid] - v;
}

__global__ void k_scan3() {   // 98 blocks x 1024: rowptr + cursor
    __shared__ int sm[1024];
    int b = blockIdx.x, tid = threadIdx.x;
    int i = b * 1024 + tid;
    int v = (i < NN) ? g_deg[i] : 0;
    sm[tid] = v; __syncthreads();
    for (int o = 1; o < 1024; o <<= 1) {
        int t = (tid >= o) ? sm[tid - o] : 0;
        __syncthreads();
        sm[tid] += t;
        __syncthreads();
    }
    if (i < NN) {
        int r = g_boff[b] + sm[tid] - v;   // exclusive
        g_rowptr[i] = r;
        g_cur[i] = r;
    }
}

__global__ void k_fill(const int* __restrict__ ei, const int* __restrict__ ea) {
    int e = blockIdx.x * 256 + threadIdx.x;
    if (e >= EE) return;
    int dst = __ldg(&ei[EE + e]);
    int p = atomicAdd(&g_cur[dst], 1);
    unsigned pk = (unsigned)__ldg(&ei[e])
                | ((unsigned)__ldg(&ea[e * 3 + 0]) << 17)
                | ((unsigned)__ldg(&ea[e * 3 + 1]) << 20)
                | ((unsigned)__ldg(&ea[e * 3 + 2]) << 23);
    g_epk[p] = pk;
}

// ====== gather: g_m[n] = hin[n] + sum_e relu(hin[src]+bond_emb)+eps =======
// half-warp (16 lanes, float4) per node; edge loop unrolled x8 for MLP=8
#define GATHER_BLOCKS 3125
__global__ void __launch_bounds__(256) k_gather(int use_h2,
                                                const float4* __restrict__ btab4) {
    __shared__ float4 comb[960];   // 60 combos x 16 float4 = 15KB
    int tid = threadIdx.x;
    for (int i = tid; i < 960; i += 256) {
        int c = i >> 4, f = i & 15;
        int a0 = c % 5, t = c / 5, a1 = t % 6, a2 = t / 6;
        float4 v0 = __ldg(&btab4[a0 * 16 + f]);
        float4 v1 = __ldg(&btab4[(5 + a1) * 16 + f]);
        float4 v2 = __ldg(&btab4[(11 + a2) * 16 + f]);
        comb[i] = make_float4(v0.x + v1.x + v2.x, v0.y + v1.y + v2.y,
                              v0.z + v1.z + v2.z, v0.w + v1.w + v2.w);
    }
    __syncthreads();

    const float4* __restrict__ hin =
        use_h2 ? (const float4*)g_h2 : (const float4*)g_h;

    int lane = tid & 15;         // feature quad
    int sub  = tid >> 4;         // 16 half-warps per block
    int n = blockIdx.x * 16 + sub;
    // prefetch CSR metadata for the first node
    int start = (n < NN) ? __ldg(&g_rowptr[n]) : 0;
    int deg   = (n < NN) ? __ldg(&g_deg[n])    : 0;
    for (; n < NN; ) {
        int nn = n + GATHER_BLOCKS * 16;
        int nstart = (nn < NN) ? __ldg(&g_rowptr[nn]) : 0;
        int ndeg   = (nn < NN) ? __ldg(&g_deg[nn])    : 0;

        float4 acc = __ldg(&hin[n * 16 + lane]);
        int j = 0;
        for (; j + 8 <= deg; j += 8) {
            unsigned pk[8];
            float4 hv[8];
#pragma unroll
            for (int t = 0; t < 8; t++) pk[t] = __ldg(&g_epk[start + j + t]);
#pragma unroll
            for (int t = 0; t < 8; t++)
                hv[t] = __ldg(&hin[(pk[t] & 0x1FFFF) * 16 + lane]);
#pragma unroll
            for (int t = 0; t < 8; t++) {
                int c = ((pk[t] >> 17) & 7) + 5 * ((pk[t] >> 20) & 7)
                      + 30 * ((pk[t] >> 23) & 1);
                float4 e = comb[c * 16 + lane];
                acc.x += fmaxf(hv[t].x + e.x, 0.f) + EPS_GEN;
                acc.y += fmaxf(hv[t].y + e.y, 0.f) + EPS_GEN;
                acc.z += fmaxf(hv[t].z + e.z, 0.f) + EPS_GEN;
                acc.w += fmaxf(hv[t].w + e.w, 0.f) + EPS_GEN;
            }
        }
        if (j + 4 <= deg) {
            unsigned pk[4];
            float4 hv[4];
#pragma unroll
            for (int t = 0; t < 4; t++) pk[t] = __ldg(&g_epk[start + j + t]);
#pragma unroll
            for (int t = 0; t < 4; t++)
                hv[t] = __ldg(&hin[(pk[t] & 0x1FFFF) * 16 + lane]);
#pragma unroll
            for (int t = 0; t < 4; t++) {
                int c = ((pk[t] >> 17) & 7) + 5 * ((pk[t] >> 20) & 7)
                      + 30 * ((pk[t] >> 23) & 1);
                float4 e = comb[c * 16 + lane];
                acc.x += fmaxf(hv[t].x + e.x, 0.f) + EPS_GEN;
                acc.y += fmaxf(hv[t].y + e.y, 0.f) + EPS_GEN;
                acc.z += fmaxf(hv[t].z + e.z, 0.f) + EPS_GEN;
                acc.w += fmaxf(hv[t].w + e.w, 0.f) + EPS_GEN;
            }
            j += 4;
        }
        for (; j < deg; j++) {
            unsigned p = __ldg(&g_epk[start + j]);
            float4 h = __ldg(&hin[(p & 0x1FFFF) * 16 + lane]);
            int c = ((p >> 17) & 7) + 5 * ((p >> 20) & 7) + 30 * ((p >> 23) & 1);
            float4 e = comb[c * 16 + lane];
            acc.x += fmaxf(h.x + e.x, 0.f) + EPS_GEN;
            acc.y += fmaxf(h.y + e.y, 0.f) + EPS_GEN;
            acc.z += fmaxf(h.z + e.z, 0.f) + EPS_GEN;
            acc.w += fmaxf(h.w + e.w, 0.f) + EPS_GEN;
        }
        ((float4*)g_m)[n * 16 + lane] = acc;
        n = nn; start = nstart; deg = ndeg;
    }
}

// ---------------- g_m @ W + b (+res) -> g_h ; fused BN stats --------------
__global__ void __launch_bounds__(256) k_matmul(int layer0,
                                                const float* __restrict__ W,
                                                const float* __restrict__ bias) {
    __shared__ __align__(16) float W_sh[64 * 64];
    __shared__ float in_sh[64][65];
    __shared__ float s_sum[64], s_sq[64];
    int tid = threadIdx.x;
    int base = blockIdx.x * 64;
    {
        const float4* W4 = (const float4*)W;
        float4* Ws4 = (float4*)W_sh;
#pragma unroll
        for (int i = 0; i < 4; i++) Ws4[tid + i * 256] = __ldg(&W4[tid + i * 256]);
    }
#pragma unroll
    for (int i = 0; i < 16; i++) {
        int idx = tid + i * 256;
        int r = idx >> 6, f = idx & 63;
        int row = base + r;
        in_sh[r][f] = (row < NN) ? g_m[row * 64 + f] : 0.f;
    }
    if (tid < 64) { s_sum[tid] = 0.f; s_sq[tid] = 0.f; }
    __syncthreads();

    int ng = tid >> 4, cg = tid & 15;
    float acc[4][4];
#pragma unroll
    for (int i = 0; i < 4; i++)
#pragma unroll
        for (int j = 0; j < 4; j++) acc[i][j] = 0.f;
#pragma unroll 8
    for (int k = 0; k < 64; k++) {
        float4 w = *(const float4*)&W_sh[k * 64 + cg * 4];
#pragma unroll
        for (int i = 0; i < 4; i++) {
            float iv = in_sh[ng * 4 + i][k];
            acc[i][0] = fmaf(iv, w.x, acc[i][0]);
            acc[i][1] = fmaf(iv, w.y, acc[i][1]);
            acc[i][2] = fmaf(iv, w.z, acc[i][2]);
            acc[i][3] = fmaf(iv, w.w, acc[i][3]);
        }
    }
    float4 bv = __ldg((const float4*)bias + cg);
    float csum[4] = {0, 0, 0, 0}, csq[4] = {0, 0, 0, 0};
#pragma unroll
    for (int i = 0; i < 4; i++) {
        int row = base + ng * 4 + i;
        if (row < NN) {
            float4 o;
            o.x = acc[i][0] + bv.x; o.y = acc[i][1] + bv.y;
            o.z = acc[i][2] + bv.z; o.w = acc[i][3] + bv.w;
            if (!layer0) {
                float4 r = *((const float4*)g_h + row * 16 + cg);
                o.x += r.x; o.y += r.y; o.z += r.z; o.w += r.w;
            }
            *((float4*)g_h + row * 16 + cg) = o;
            csum[0] += o.x; csq[0] += o.x * o.x;
            csum[1] += o.y; csq[1] += o.y * o.y;
            csum[2] += o.z; csq[2] += o.z * o.z;
            csum[3] += o.w; csq[3] += o.w * o.w;
        }
    }
#pragma unroll
    for (int j = 0; j < 4; j++) {
        atomicAdd(&s_sum[cg * 4 + j], csum[j]);
        atomicAdd(&s_sq [cg * 4 + j], csq[j]);
    }
    __syncthreads();
    if (tid < 64) {
        atomicAdd(&g_sum[tid], s_sum[tid]);
        atomicAdd(&g_sq [tid], s_sq[tid]);
    }
}

// ---- pool relu(BN(h)) -> vt (read-only); zero vn stats -------------------
__global__ void __launch_bounds__(256) k_bn_pool(const float* __restrict__ gamma,
                                                 const float* __restrict__ beta,
                                                 const int* __restrict__ batch) {
    int tid = threadIdx.x;
    int f = tid & 63;
    float mu = g_sum[f] * (1.f / NN);
    float var = g_sq[f] * (1.f / NN) - mu * mu;
    float ga = gamma[f] * rsqrtf(var + EPS_BN);
    float sh = beta[f] - mu * ga;
    if (blockIdx.x == 0 && tid < 128) { g_vnsA[tid] = 0.f; g_vnsB[tid] = 0.f; }
    int base = blockIdx.x * 256;
    int r0 = base + (tid >> 6);
    int rend = min(base + 256, NN);
    int cur = -1;
    float acc = 0.f;
    for (int r = r0; r < rend; r += 4) {
        float v = fmaxf(fmaf(g_h[r * 64 + f], ga, sh), 0.f);
        int b = __ldg(&batch[r]);
        if (b != cur) {
            if (cur >= 0) atomicAdd(&g_vt[cur * 64 + f], acc);
            cur = b; acc = v;
        } else acc += v;
    }
    if (cur >= 0) atomicAdd(&g_vt[cur * 64 + f], acc);
}

// ---- virtual node MLP ----------------------------------------------------
__global__ void k_vn_a(const float* __restrict__ W1, const float* __restrict__ b1) {
    __shared__ float row[64];
    int g = blockIdx.x, j = threadIdx.x;
    row[j] = g_vt[g * 64 + j] + g_vn[g * 64 + j];
    __syncthreads();
    float acc = __ldg(&b1[j]);
#pragma unroll
    for (int k = 0; k < 64; k++) acc = fmaf(row[k], __ldg(&W1[k * 64 + j]), acc);
    g_vt[g * 64 + j] = acc;
    atomicAdd(&g_vnsA[j], acc);
    atomicAdd(&g_vnsA[64 + j], acc * acc);
}

__global__ void k_vn_b(const float* __restrict__ g1, const float* __restrict__ be1,
                       const float* __restrict__ W2, const float* __restrict__ b2) {
    __shared__ float z[64];
    int g = blockIdx.x, j = threadIdx.x;
    float mu = g_vnsA[j] * (1.f / GG);
    float var = g_vnsA[64 + j] * (1.f / GG) - mu * mu;
    float ga = __ldg(&g1[j]) * rsqrtf(var + EPS_BN);
    float y = g_vt[g * 64 + j];
    z[j] = fmaxf((y - mu) * ga + __ldg(&be1[j]), 0.f);
    __syncthreads();
    float acc = __ldg(&b2[j]);
#pragma unroll
    for (int k = 0; k < 64; k++) acc = fmaf(z[k], __ldg(&W2[k * 64 + j]), acc);
    g_vt[g * 64 + j] = acc;
    atomicAdd(&g_vnsB[j], acc);
    atomicAdd(&g_vnsB[64 + j], acc * acc);
}

// ---- vn = relu(BN2(y2)); also precompute node-BN coeffs ga/sh ------------
__global__ void k_vn_c(const float* __restrict__ g2, const float* __restrict__ be2,
                       const float* __restrict__ gamma, const float* __restrict__ beta) {
    int i = blockIdx.x * blockDim.x + threadIdx.x;
    if (i < HD) {   // node-BN coefficients for k_h2
        float mu = g_sum[i] * (1.f / NN);
        float var = g_sq[i] * (1.f / NN) - mu * mu;
        float ga = gamma[i] * rsqrtf(var + EPS_BN);
        g_ga[i] = ga;
        g_sh[i] = beta[i] - mu * ga;
    }
    if (i >= GG * HD) return;
    int j = i & 63;
    float mu = g_vnsB[j] * (1.f / GG);
    float var = g_vnsB[64 + j] * (1.f / GG) - mu * mu;
    float ga = __ldg(&g2[j]) * rsqrtf(var + EPS_BN);
    g_vn[i] = fmaxf((g_vt[i] - mu) * ga + __ldg(&be2[j]), 0.f);
}

// ---- h2 = relu(BN(h)) + vn[batch]; zero node stats + vt ------------------
__global__ void __launch_bounds__(256) k_h2(const int* __restrict__ batch) {
    int idx = blockIdx.x * 256 + threadIdx.x;   // float4 index
    if (blockIdx.x == 0 && threadIdx.x < 64) {
        g_sum[threadIdx.x] = 0.f;
        g_sq[threadIdx.x] = 0.f;
    }
    if (blockIdx.x == 1) {
        for (int i = threadIdx.x; i < GG * HD; i += 256) g_vt[i] = 0.f;
    }
    if (idx >= NN * 16) return;
    int n = idx >> 4, fq = idx & 15;
    int b = __ldg(&batch[n]);
    float4 h = ((const float4*)g_h)[idx];
    float4 vn = __ldg((const float4*)g_vn + b * 16 + fq);
    float4 ga = *((const float4*)g_ga + fq);
    float4 sh = *((const float4*)g_sh + fq);
    float4 o;
    o.x = fmaxf(fmaf(h.x, ga.x, sh.x), 0.f) + vn.x;
    o.y = fmaxf(fmaf(h.y, ga.y, sh.y), 0.f) + vn.y;
    o.z = fmaxf(fmaf(h.z, ga.z, sh.z), 0.f) + vn.z;
    o.w = fmaxf(fmaf(h.w, ga.w, sh.w), 0.f) + vn.w;
    ((float4*)g_h2)[idx] = o;
}

// ---- pool: vt[g] = segment_sum(h) (raw h; final readout) -----------------
__global__ void __launch_bounds__(256) k_pool(const int* __restrict__ batch) {
    int tid = threadIdx.x;
    int f = tid & 63;
    int base = blockIdx.x * 256;
    int r0 = base + (tid >> 6);
    int rend = min(base + 256, NN);
    int cur = -1;
    float acc = 0.f;
    for (int r = r0; r < rend; r += 4) {
        float v = g_h[r * 64 + f];
        int b = __ldg(&batch[r]);
        if (b != cur) {
            if (cur >= 0) atomicAdd(&g_vt[cur * 64 + f], acc);
            cur = b; acc = v;
        } else acc += v;
    }
    if (cur >= 0) atomicAdd(&g_vt[cur * 64 + f], acc);
}

// ---- out = (vt/clip(cnt,1) - mu)*rstd*gamma + beta -----------------------
__global__ void k_final(float* __restrict__ out,
                        const float* __restrict__ gamma,
                        const float* __restrict__ beta) {
    int i = blockIdx.x * blockDim.x + threadIdx.x;
    if (i >= GG * HD) return;
    int g = i >> 6, f = i & 63;
    float mu = g_sum[f] * (1.f / NN);
    float var = g_sq[f] * (1.f / NN) - mu * mu;
    float rstd = rsqrtf(var + EPS_BN);
    float c = fmaxf(g_cnt[g], 1.f);
    out[i] = (g_vt[i] / c - mu) * rstd * __ldg(&gamma[f]) + __ldg(&beta[f]);
}

// =========================================================================
extern "C" void kernel_launch(void* const* d_in, const int* in_sizes, int n_in,
                              void* d_out, int out_size) {
    const float* atab  = (const float*)d_in[0];
    const float* btab  = (const float*)d_in[1];
    const float* vn0   = (const float*)d_in[2];
    const float* gcnW  = (const float*)d_in[3];
    const float* gcnb  = (const float*)d_in[4];
    const float* ngam  = (const float*)d_in[5];
    const float* nbet  = (const float*)d_in[6];
    const float* vnW1  = (const float*)d_in[7];
    const float* vnb1  = (const float*)d_in[8];
    const float* vng1  = (const float*)d_in[9];
    const float* vnbe1 = (const float*)d_in[10];
    const float* vnW2  = (const float*)d_in[11];
    const float* vnb2  = (const float*)d_in[12];
    const float* vng2  = (const float*)d_in[13];
    const float* vnbe2 = (const float*)d_in[14];
    const int*   x     = (const int*)d_in[15];
    const int*   ei    = (const int*)d_in[16];
    const int*   ea    = (const int*)d_in[17];
    const int*   batch = (const int*)d_in[18];
    float* out = (float*)d_out;

    const int MM_BLOCKS = (NN + 63) / 64;          // 1563
    const int SC_BLOCKS = (NN + 1023) / 1024;      // 98  (scans)
    const int PL_BLOCKS = (NN + 255) / 256;        // 391 (pool passes)
    const int E_BLOCKS  = (EE + 255) / 256;        // 3907
    const int H2_BLOCKS = (NN * 16 + 255) / 256;   // 6250

    // init + CSR build (integer atomics only)
    k_init<<<(NN + 255) / 256, 256>>>(vn0);
    k_cnt<<<(NN + 32 * 256 - 1) / (32 * 256), 256>>>(batch);
    k_atom<<<(NN * 16 + 255) / 256, 256>>>((const float4*)atab, x, (const float4*)vn0);
    k_hist<<<E_BLOCKS, 256>>>(ei);
    k_scan1<<<SC_BLOCKS, 1024>>>();
    k_scan2<<<1, 128>>>();
    k_scan3<<<SC_BLOCKS, 1024>>>();
    k_fill<<<E_BLOCKS, 256>>>(ei, ea);

    // layer 0: conv only (reads g_h)
    k_gather<<<GATHER_BLOCKS, 256>>>(0, (const float4*)btab);
    k_matmul<<<MM_BLOCKS, 256>>>(1, gcnW, gcnb);

    // layers 1..6: BN->ReLU->vnode->conv->+res
    for (int l = 1; l < 7; l++) {
        int li = l - 1;
        k_bn_pool<<<PL_BLOCKS, 256>>>(ngam + li * 64, nbet + li * 64, batch);
        k_vn_a<<<GG, 64>>>(vnW1 + li * 4096, vnb1 + li * 64);
        k_vn_b<<<GG, 64>>>(vng1 + li * 64, vnbe1 + li * 64,
                           vnW2 + li * 4096, vnb2 + li * 64);
        k_vn_c<<<(GG * HD + 255) / 256, 256>>>(vng2 + li * 64, vnbe2 + li * 64,
                                               ngam + li * 64, nbet + li * 64);
        k_h2<<<H2_BLOCKS, 256>>>(batch);
        k_gather<<<GATHER_BLOCKS, 256>>>(1, (const float4*)btab);
        k_matmul<<<MM_BLOCKS, 256>>>(0, gcnW + l * 4096, gcnb + l * 64);
    }

    // readout: mean pool of h, BN applied as affine on pooled mean
    k_pool<<<PL_BLOCKS, 256>>>(batch);
    k_final<<<(GG * HD + 255) / 256, 256>>>(out, ngam + 6 * 64, nbet + 6 * 64);
}

// round 15
// speedup vs baseline: 1.0541x; 1.0335x over previous
#include <cuda_runtime.h>

#define NN 100000      // nodes
#define EE 1000000     // edges
#define HD 64          // hidden
#define GG 512         // graphs
#define EPS_GEN 1e-7f
#define EPS_BN  1e-5f

// ---------------- scratch (device globals; no allocations) ----------------
__device__ float g_h [NN * HD];
__device__ float g_h2[NN * HD];
__device__ float g_m [NN * HD];   // conv input: h_in + aggregated messages
__device__ float g_vt[GG * HD];
__device__ float g_vn[GG * HD];
__device__ float g_sum[HD];
__device__ float g_sq [HD];
__device__ float g_vnsA[2 * HD];
__device__ float g_vnsB[2 * HD];
__device__ float g_cnt[GG];
// CSR by destination
__device__ int g_deg[NN];
__device__ int g_rowptr[NN];
__device__ int g_cur[NN];
__device__ int g_bsum[128];
__device__ int g_boff[128];
__device__ unsigned g_epk[EE];    // packed: src | a0<<17 | a1<<20 | a2<<23

// ---------------- boot: atom encoder + deg/cnt/vn/vt/stats init -----------
__global__ void k_boot(const float4* __restrict__ atab,
                       const int* __restrict__ x,
                       const float4* __restrict__ vn0) {
    int i = blockIdx.x * 256 + threadIdx.x;
    int n = i >> 4, lane = i & 15;
    if (n < NN) {
        const int aoff[9] = {0, 119, 124, 136, 148, 158, 164, 170, 172};
        float4 a = __ldg(&vn0[lane]);
#pragma unroll
        for (int k = 0; k < 9; k++) {
            int idx = __ldg(&x[n * 9 + k]) + aoff[k];
            float4 v = __ldg(&atab[idx * 16 + lane]);
            a.x += v.x; a.y += v.y; a.z += v.z; a.w += v.w;
        }
        ((float4*)g_h)[n * 16 + lane] = a;
    }
    if (i < NN) g_deg[i] = 0;
    if (i < GG) g_cnt[i] = 0.f;
    if (i < GG * HD) {
        g_vn[i] = ((const float*)vn0)[i & 63];
        g_vt[i] = 0.f;
    }
    if (i < HD) { g_sum[i] = 0.f; g_sq[i] = 0.f; }
}

// ---------------- node counts per graph (after k_boot zeroed cnt) ---------
__global__ void k_cnt(const int* __restrict__ batch) {
    int t = blockIdx.x * blockDim.x + threadIdx.x;
    int base = t * 32;
    if (base >= NN) return;
    int end = min(base + 32, NN);
    int cur = batch[base];
    float acc = 0.f;
    for (int r = base; r < end; r++) {
        int b = batch[r];
        if (b != cur) { atomicAdd(&g_cnt[cur], acc); cur = b; acc = 0.f; }
        acc += 1.f;
    }
    atomicAdd(&g_cnt[cur], acc);
}

// ================= CSR build (per call; edges static within call) =========
__global__ void k_hist(const int* __restrict__ ei) {
    int e = blockIdx.x * 256 + threadIdx.x;
    if (e >= EE) return;
    atomicAdd(&g_deg[__ldg(&ei[EE + e])], 1);
}

__global__ void k_scan1() {   // 98 blocks x 1024: chunk sums
    __shared__ int ws[32];
    int b = blockIdx.x, tid = threadIdx.x;
    int i = b * 1024 + tid;
    int v = (i < NN) ? g_deg[i] : 0;
    int s = v;
#pragma unroll
    for (int o = 16; o; o >>= 1) s += __shfl_down_sync(~0u, s, o);
    if ((tid & 31) == 0) ws[tid >> 5] = s;
    __syncthreads();
    if (tid < 32) {
        int t = ws[tid];
#pragma unroll
        for (int o = 16; o; o >>= 1) t += __shfl_down_sync(~0u, t, o);
        if (tid == 0) g_bsum[b] = t;
    }
}

__global__ void k_scan2() {   // 1 block x 128: exclusive scan of chunk sums
    __shared__ int sm[128];
    int tid = threadIdx.x;
    int nb = (NN + 1023) / 1024;
    int v = (tid < nb) ? g_bsum[tid] : 0;
    sm[tid] = v; __syncthreads();
    for (int o = 1; o < 128; o <<= 1) {
        int t = (tid >= o) ? sm[tid - o] : 0;
        __syncthreads();
        sm[tid] += t;
        __syncthreads();
    }
    g_boff[tid] = sm[tid] - v;
}

__global__ void k_scan3() {   // 98 blocks x 1024: rowptr + cursor
    __shared__ int sm[1024];
    int b = blockIdx.x, tid = threadIdx.x;
    int i = b * 1024 + tid;
    int v = (i < NN) ? g_deg[i] : 0;
    sm[tid] = v; __syncthreads();
    for (int o = 1; o < 1024; o <<= 1) {
        int t = (tid >= o) ? sm[tid - o] : 0;
        __syncthreads();
        sm[tid] += t;
        __syncthreads();
    }
    if (i < NN) {
        int r = g_boff[b] + sm[tid] - v;   // exclusive
        g_rowptr[i] = r;
        g_cur[i] = r;
    }
}

__global__ void k_fill(const int* __restrict__ ei, const int* __restrict__ ea) {
    int e = blockIdx.x * 256 + threadIdx.x;
    if (e >= EE) return;
    int dst = __ldg(&ei[EE + e]);
    int p = atomicAdd(&g_cur[dst], 1);
    unsigned pk = (unsigned)__ldg(&ei[e])
                | ((unsigned)__ldg(&ea[e * 3 + 0]) << 17)
                | ((unsigned)__ldg(&ea[e * 3 + 1]) << 20)
                | ((unsigned)__ldg(&ea[e * 3 + 2]) << 23);
    g_epk[p] = pk;
}

// ====== gather: g_m[n] = hin[n] + sum_e relu(hin[src]+bond_emb)+eps =======
// half-warp (16 lanes, float4) per node; x4 edge unroll (R10 shape).
// Also zeroes vt + node stats for the next layer (blocks 0/1).
#define GATHER_BLOCKS 3125
__global__ void __launch_bounds__(256) k_gather(int use_h2,
                                                const float4* __restrict__ btab4) {
    __shared__ float4 comb[960];   // 60 combos x 16 float4 = 15KB
    int tid = threadIdx.x;
    if (blockIdx.x == 0) {
        for (int i = tid; i < GG * HD; i += 256) g_vt[i] = 0.f;
    }
    if (blockIdx.x == 1 && tid < 64) { g_sum[tid] = 0.f; g_sq[tid] = 0.f; }
    for (int i = tid; i < 960; i += 256) {
        int c = i >> 4, f = i & 15;
        int a0 = c % 5, t = c / 5, a1 = t % 6, a2 = t / 6;
        float4 v0 = __ldg(&btab4[a0 * 16 + f]);
        float4 v1 = __ldg(&btab4[(5 + a1) * 16 + f]);
        float4 v2 = __ldg(&btab4[(11 + a2) * 16 + f]);
        comb[i] = make_float4(v0.x + v1.x + v2.x, v0.y + v1.y + v2.y,
                              v0.z + v1.z + v2.z, v0.w + v1.w + v2.w);
    }
    __syncthreads();

    const float4* __restrict__ hin =
        use_h2 ? (const float4*)g_h2 : (const float4*)g_h;

    int lane = tid & 15;         // feature quad
    int sub  = tid >> 4;         // 16 half-warps per block
    for (int n = blockIdx.x * 16 + sub; n < NN; n += GATHER_BLOCKS * 16) {
        int start = __ldg(&g_rowptr[n]);
        int deg   = __ldg(&g_deg[n]);
        float4 acc = __ldg(&hin[n * 16 + lane]);
        int j = 0;
        for (; j + 4 <= deg; j += 4) {
            unsigned pk[4];
            float4 hv[4];
#pragma unroll
            for (int t = 0; t < 4; t++) pk[t] = __ldg(&g_epk[start + j + t]);
#pragma unroll
            for (int t = 0; t < 4; t++)
                hv[t] = __ldg(&hin[(pk[t] & 0x1FFFF) * 16 + lane]);
#pragma unroll
            for (int t = 0; t < 4; t++) {
                int c = ((pk[t] >> 17) & 7) + 5 * ((pk[t] >> 20) & 7)
                      + 30 * ((pk[t] >> 23) & 1);
                float4 e = comb[c * 16 + lane];
                acc.x += fmaxf(hv[t].x + e.x, 0.f) + EPS_GEN;
                acc.y += fmaxf(hv[t].y + e.y, 0.f) + EPS_GEN;
                acc.z += fmaxf(hv[t].z + e.z, 0.f) + EPS_GEN;
                acc.w += fmaxf(hv[t].w + e.w, 0.f) + EPS_GEN;
            }
        }
        for (; j < deg; j++) {
            unsigned p = __ldg(&g_epk[start + j]);
            float4 h = __ldg(&hin[(p & 0x1FFFF) * 16 + lane]);
            int c = ((p >> 17) & 7) + 5 * ((p >> 20) & 7) + 30 * ((p >> 23) & 1);
            float4 e = comb[c * 16 + lane];
            acc.x += fmaxf(h.x + e.x, 0.f) + EPS_GEN;
            acc.y += fmaxf(h.y + e.y, 0.f) + EPS_GEN;
            acc.z += fmaxf(h.z + e.z, 0.f) + EPS_GEN;
            acc.w += fmaxf(h.w + e.w, 0.f) + EPS_GEN;
        }
        ((float4*)g_m)[n * 16 + lane] = acc;
    }
}

// ---------------- g_m @ W + b (+res) -> g_h ; fused BN stats --------------
// float4 operand loads on both sides (in_sh padded to 68 floats/row).
// NOTE: macro parameter named 'wv' so member access '.w' doesn't collide.
#define ACC1(i, s, wv) \
    acc[i][0] = fmaf(s, wv.x, acc[i][0]); acc[i][1] = fmaf(s, wv.y, acc[i][1]); \
    acc[i][2] = fmaf(s, wv.z, acc[i][2]); acc[i][3] = fmaf(s, wv.w, acc[i][3]);

__global__ void __launch_bounds__(256) k_matmul(int layer0,
                                                const float* __restrict__ W,
                                                const float* __restrict__ bias) {
    __shared__ __align__(16) float W_sh[64 * 64];
    __shared__ __align__(16) float in_sh[64][68];
    __shared__ float s_sum[64], s_sq[64];
    int tid = threadIdx.x;
    int base = blockIdx.x * 64;
    {
        const float4* W4 = (const float4*)W;
        float4* Ws4 = (float4*)W_sh;
#pragma unroll
        for (int i = 0; i < 4; i++) Ws4[tid + i * 256] = __ldg(&W4[tid + i * 256]);
    }
#pragma unroll
    for (int i = 0; i < 16; i++) {
        int idx = tid + i * 256;
        int r = idx >> 6, f = idx & 63;
        int row = base + r;
        in_sh[r][f] = (row < NN) ? g_m[row * 64 + f] : 0.f;
    }
    if (tid < 64) { s_sum[tid] = 0.f; s_sq[tid] = 0.f; }
    __syncthreads();

    int ng = tid >> 4, cg = tid & 15;
    const float4* W_sh4 = (const float4*)W_sh;
    float acc[4][4];
#pragma unroll
    for (int i = 0; i < 4; i++)
#pragma unroll
        for (int j = 0; j < 4; j++) acc[i][j] = 0.f;

#pragma unroll 4
    for (int k4 = 0; k4 < 16; k4++) {
        float4 iv0 = *(const float4*)&in_sh[ng * 4 + 0][k4 * 4];
        float4 iv1 = *(const float4*)&in_sh[ng * 4 + 1][k4 * 4];
        float4 iv2 = *(const float4*)&in_sh[ng * 4 + 2][k4 * 4];
        float4 iv3 = *(const float4*)&in_sh[ng * 4 + 3][k4 * 4];
        float4 w0 = W_sh4[(k4 * 4 + 0) * 16 + cg];
        float4 w1 = W_sh4[(k4 * 4 + 1) * 16 + cg];
        float4 w2 = W_sh4[(k4 * 4 + 2) * 16 + cg];
        float4 w3 = W_sh4[(k4 * 4 + 3) * 16 + cg];
        ACC1(0, iv0.x, w0) ACC1(0, iv0.y, w1) ACC1(0, iv0.z, w2) ACC1(0, iv0.w, w3)
        ACC1(1, iv1.x, w0) ACC1(1, iv1.y, w1) ACC1(1, iv1.z, w2) ACC1(1, iv1.w, w3)
        ACC1(2, iv2.x, w0) ACC1(2, iv2.y, w1) ACC1(2, iv2.z, w2) ACC1(2, iv2.w, w3)
        ACC1(3, iv3.x, w0) ACC1(3, iv3.y, w1) ACC1(3, iv3.z, w2) ACC1(3, iv3.w, w3)
    }
    float4 bv = __ldg((const float4*)bias + cg);
    float csum[4] = {0, 0, 0, 0}, csq[4] = {0, 0, 0, 0};
#pragma unroll
    for (int i = 0; i < 4; i++) {
        int row = base + ng * 4 + i;
        if (row < NN) {
            float4 o;
            o.x = acc[i][0] + bv.x; o.y = acc[i][1] + bv.y;
            o.z = acc[i][2] + bv.z; o.w = acc[i][3] + bv.w;
            if (!layer0) {
                float4 r = *((const float4*)g_h + row * 16 + cg);
                o.x += r.x; o.y += r.y; o.z += r.z; o.w += r.w;
            }
            *((float4*)g_h + row * 16 + cg) = o;
            csum[0] += o.x; csq[0] += o.x * o.x;
            csum[1] += o.y; csq[1] += o.y * o.y;
            csum[2] += o.z; csq[2] += o.z * o.z;
            csum[3] += o.w; csq[3] += o.w * o.w;
        }
    }
#pragma unroll
    for (int j = 0; j < 4; j++) {
        atomicAdd(&s_sum[cg * 4 + j], csum[j]);
        atomicAdd(&s_sq [cg * 4 + j], csq[j]);
    }
    __syncthreads();
    if (tid < 64) {
        atomicAdd(&g_sum[tid], s_sum[tid]);
        atomicAdd(&g_sq [tid], s_sq[tid]);
    }
}

// ---- pool relu(BN(h)) -> vt (read-only); zero vn stats -------------------
__global__ void __launch_bounds__(256) k_bn_pool(const float* __restrict__ gamma,
                                                 const float* __restrict__ beta,
                                                 const int* __restrict__ batch) {
    int tid = threadIdx.x;
    int f = tid & 63;
    float mu = g_sum[f] * (1.f / NN);
    float var = g_sq[f] * (1.f / NN) - mu * mu;
    float ga = gamma[f] * rsqrtf(var + EPS_BN);
    float sh = beta[f] - mu * ga;
    if (blockIdx.x == 0 && tid < 128) { g_vnsA[tid] = 0.f; g_vnsB[tid] = 0.f; }
    int base = blockIdx.x * 256;
    int r0 = base + (tid >> 6);
    int rend = min(base + 256, NN);
    int cur = -1;
    float acc = 0.f;
    for (int r = r0; r < rend; r += 4) {
        float v = fmaxf(fmaf(g_h[r * 64 + f], ga, sh), 0.f);
        int b = __ldg(&batch[r]);
        if (b != cur) {
            if (cur >= 0) atomicAdd(&g_vt[cur * 64 + f], acc);
            cur = b; acc = v;
        } else acc += v;
    }
    if (cur >= 0) atomicAdd(&g_vt[cur * 64 + f], acc);
}

// ---- virtual node MLP ----------------------------------------------------
__global__ void k_vn_a(const float* __restrict__ W1, const float* __restrict__ b1) {
    __shared__ float row[64];
    int g = blockIdx.x, j = threadIdx.x;
    row[j] = g_vt[g * 64 + j] + g_vn[g * 64 + j];
    __syncthreads();
    float acc = __ldg(&b1[j]);
#pragma unroll
    for (int k = 0; k < 64; k++) acc = fmaf(row[k], __ldg(&W1[k * 64 + j]), acc);
    g_vt[g * 64 + j] = acc;
    atomicAdd(&g_vnsA[j], acc);
    atomicAdd(&g_vnsA[64 + j], acc * acc);
}

__global__ void k_vn_b(const float* __restrict__ g1, const float* __restrict__ be1,
                       const float* __restrict__ W2, const float* __restrict__ b2) {
    __shared__ float z[64];
    int g = blockIdx.x, j = threadIdx.x;
    float mu = g_vnsA[j] * (1.f / GG);
    float var = g_vnsA[64 + j] * (1.f / GG) - mu * mu;
    float ga = __ldg(&g1[j]) * rsqrtf(var + EPS_BN);
    float y = g_vt[g * 64 + j];
    z[j] = fmaxf((y - mu) * ga + __ldg(&be1[j]), 0.f);
    __syncthreads();
    float acc = __ldg(&b2[j]);
#pragma unroll
    for (int k = 0; k < 64; k++) acc = fmaf(z[k], __ldg(&W2[k * 64 + j]), acc);
    g_vt[g * 64 + j] = acc;
    atomicAdd(&g_vnsB[j], acc);
    atomicAdd(&g_vnsB[64 + j], acc * acc);
}

// ---- h2 = relu(BN(h)) + relu(BN2(vt))[batch]; persist vn (blocks 0-127) --
__global__ void __launch_bounds__(256) k_h2(const int* __restrict__ batch,
                                            const float* __restrict__ gamma,
                                            const float* __restrict__ beta,
                                            const float* __restrict__ g2,
                                            const float* __restrict__ be2) {
    __shared__ __align__(16) float s_ga[64], s_sh[64], s_ga2[64], s_sh2[64];
    int tid = threadIdx.x;
    if (tid < 64) {                       // node-BN coeffs
        float mu = g_sum[tid] * (1.f / NN);
        float var = g_sq[tid] * (1.f / NN) - mu * mu;
        float ga = __ldg(&gamma[tid]) * rsqrtf(var + EPS_BN);
        s_ga[tid] = ga;
        s_sh[tid] = __ldg(&beta[tid]) - mu * ga;
    } else if (tid < 128) {               // vn BN2 coeffs
        int f = tid - 64;
        float mu = g_vnsB[f] * (1.f / GG);
        float var = g_vnsB[64 + f] * (1.f / GG) - mu * mu;
        float ga = __ldg(&g2[f]) * rsqrtf(var + EPS_BN);
        s_ga2[f] = ga;
        s_sh2[f] = __ldg(&be2[f]) - mu * ga;
    }
    __syncthreads();

    // persist vn for next layer's k_vn_a (blocks 0..127 cover GG*HD)
    if (blockIdx.x < 128) {
        int i = blockIdx.x * 256 + tid;
        int f = i & 63;
        g_vn[i] = fmaxf(fmaf(g_vt[i], s_ga2[f], s_sh2[f]), 0.f);
    }

    int idx = blockIdx.x * 256 + tid;     // float4 index
    if (idx >= NN * 16) return;
    int n = idx >> 4, fq = idx & 15;
    int b = __ldg(&batch[n]);
    float4 h   = ((const float4*)g_h)[idx];
    float4 vt4 = __ldg((const float4*)g_vt + b * 16 + fq);
    float4 ga  = *(const float4*)&s_ga [fq * 4];
    float4 sh  = *(const float4*)&s_sh [fq * 4];
    float4 ga2 = *(const float4*)&s_ga2[fq * 4];
    float4 sh2 = *(const float4*)&s_sh2[fq * 4];
    float4 o;
    o.x = fmaxf(fmaf(h.x, ga.x, sh.x), 0.f) + fmaxf(fmaf(vt4.x, ga2.x, sh2.x), 0.f);
    o.y = fmaxf(fmaf(h.y, ga.y, sh.y), 0.f) + fmaxf(fmaf(vt4.y, ga2.y, sh2.y), 0.f);
    o.z = fmaxf(fmaf(h.z, ga.z, sh.z), 0.f) + fmaxf(fmaf(vt4.z, ga2.z, sh2.z), 0.f);
    o.w = fmaxf(fmaf(h.w, ga.w, sh.w), 0.f) + fmaxf(fmaf(vt4.w, ga2.w, sh2.w), 0.f);
    ((float4*)g_h2)[idx] = o;
}

// ---- pool: vt[g] = segment_sum(h) (raw h; final readout) -----------------
__global__ void __launch_bounds__(256) k_pool(const int* __restrict__ batch) {
    int tid = threadIdx.x;
    int f = tid & 63;
    int base = blockIdx.x * 256;
    int r0 = base + (tid >> 6);
    int rend = min(base + 256, NN);
    int cur = -1;
    float acc = 0.f;
    for (int r = r0; r < rend; r += 4) {
        float v = g_h[r * 64 + f];
        int b = __ldg(&batch[r]);
        if (b != cur) {
            if (cur >= 0) atomicAdd(&g_vt[cur * 64 + f], acc);
            cur = b; acc = v;
        } else acc += v;
    }
    if (cur >= 0) atomicAdd(&g_vt[cur * 64 + f], acc);
}

// ---- out = (vt/clip(cnt,1) - mu)*rstd*gamma + beta -----------------------
__global__ void k_final(float* __restrict__ out,
                        const float* __restrict__ gamma,
                        const float* __restrict__ beta) {
    int i = blockIdx.x * blockDim.x + threadIdx.x;
    if (i >= GG * HD) return;
    int g = i >> 6, f = i & 63;
    float mu = g_sum[f] * (1.f / NN);
    float var = g_sq[f] * (1.f / NN) - mu * mu;
    float rstd = rsqrtf(var + EPS_BN);
    float c = fmaxf(g_cnt[g], 1.f);
    out[i] = (g_vt[i] / c - mu) * rstd * __ldg(&gamma[f]) + __ldg(&beta[f]);
}

// =========================================================================
extern "C" void kernel_launch(void* const* d_in, const int* in_sizes, int n_in,
                              void* d_out, int out_size) {
    const float* atab  = (const float*)d_in[0];
    const float* btab  = (const float*)d_in[1];
    const float* vn0   = (const float*)d_in[2];
    const float* gcnW  = (const float*)d_in[3];
    const float* gcnb  = (const float*)d_in[4];
    const float* ngam  = (const float*)d_in[5];
    const float* nbet  = (const float*)d_in[6];
    const float* vnW1  = (const float*)d_in[7];
    const float* vnb1  = (const float*)d_in[8];
    const float* vng1  = (const float*)d_in[9];
    const float* vnbe1 = (const float*)d_in[10];
    const float* vnW2  = (const float*)d_in[11];
    const float* vnb2  = (const float*)d_in[12];
    const float* vng2  = (const float*)d_in[13];
    const float* vnbe2 = (const float*)d_in[14];
    const int*   x     = (const int*)d_in[15];
    const int*   ei    = (const int*)d_in[16];
    const int*   ea    = (const int*)d_in[17];
    const int*   batch = (const int*)d_in[18];
    float* out = (float*)d_out;

    const int MM_BLOCKS = (NN + 63) / 64;          // 1563
    const int SC_BLOCKS = (NN + 1023) / 1024;      // 98  (scans)
    const int PL_BLOCKS = (NN + 255) / 256;        // 391 (pool passes)
    const int E_BLOCKS  = (EE + 255) / 256;        // 3907
    const int H2_BLOCKS = (NN * 16 + 255) / 256;   // 6250

    // boot + CSR build (integer atomics only)
    k_boot<<<H2_BLOCKS, 256>>>((const float4*)atab, x, (const float4*)vn0);
    k_cnt<<<(NN + 32 * 256 - 1) / (32 * 256), 256>>>(batch);
    k_hist<<<E_BLOCKS, 256>>>(ei);
    k_scan1<<<SC_BLOCKS, 1024>>>();
    k_scan2<<<1, 128>>>();
    k_scan3<<<SC_BLOCKS, 1024>>>();
    k_fill<<<E_BLOCKS, 256>>>(ei, ea);

    // layer 0: conv only (reads g_h)
    k_gather<<<GATHER_BLOCKS, 256>>>(0, (const float4*)btab);
    k_matmul<<<MM_BLOCKS, 256>>>(1, gcnW, gcnb);

    // layers 1..6: BN->ReLU->vnode->conv->+res
    for (int l = 1; l < 7; l++) {
        int li = l - 1;
        k_bn_pool<<<PL_BLOCKS, 256>>>(ngam + li * 64, nbet + li * 64, batch);
        k_vn_a<<<GG, 64>>>(vnW1 + li * 4096, vnb1 + li * 64);
        k_vn_b<<<GG, 64>>>(vng1 + li * 64, vnbe1 + li * 64,
                           vnW2 + li * 4096, vnb2 + li * 64);
        k_h2<<<H2_BLOCKS, 256>>>(batch, ngam + li * 64, nbet + li * 64,
                                 vng2 + li * 64, vnbe2 + li * 64);
        k_gather<<<GATHER_BLOCKS, 256>>>(1, (const float4*)btab);
        k_matmul<<<MM_BLOCKS, 256>>>(0, gcnW + l * 4096, gcnb + l * 64);
    }

    // readout: mean pool of h, BN applied as affine on pooled mean
    k_pool<<<PL_BLOCKS, 256>>>(batch);
    k_final<<<(GG * HD + 255) / 256, 256>>>(out, ngam + 6 * 64, nbet + 6 * 64);
}